// round 1
// baseline (speedup 1.0000x reference)
#include <cuda_runtime.h>
#include <math.h>
#include <stdint.h>

#define NDIM     128
#define TABK     2048
#define BMAXF    8.0f
#define INV_BMAX 0.125f
#define ATT_SCALE 0.08838834764831845f  // 1/sqrt(128)
#define MAX_GRAPHS 10000

// -------- persistent device scratch (static allocation only) --------
__device__ float g_M[2][NDIM];               // Wq @ Wk^T   (rank-2 query projection)
__device__ float g_U2[2][NDIM];              // Wv @ W1
__device__ float g_Kb[2];                    // Wk @ bq
__device__ int   g_start[MAX_GRAPHS + 1];    // per-graph node offsets
__device__ float g_psi[2][TABK + 1][NDIM];   // charge_embed table psi_j(beta)

__device__ __forceinline__ float silu_f(float z) {
    return z / (1.0f + expf(-z));            // stable: large -z -> 0, large z -> z
}
__device__ __forceinline__ float softplus_f(float s) {
    // matches jax.nn.softplus = logaddexp(s, 0)
    return fmaxf(s, 0.0f) + log1pf(expf(-fabsf(s)));
}

// -------- tiny precompute: M, U2, Kb --------
__global__ void prep_kernel(const float* __restrict__ Wq, const float* __restrict__ bq,
                            const float* __restrict__ Wk, const float* __restrict__ Wv,
                            const float* __restrict__ W1) {
    int tid = threadIdx.x;       // 256 threads
    int j = tid >> 7, e = tid & 127;
    float m = 0.f;
    #pragma unroll 8
    for (int d = 0; d < NDIM; d++) m = fmaf(Wq[e * NDIM + d], Wk[j * NDIM + d], m);
    g_M[j][e] = m;
    float u = 0.f;
    #pragma unroll 8
    for (int ee = 0; ee < NDIM; ee++) u = fmaf(Wv[j * NDIM + ee], W1[ee * NDIM + e], u);
    g_U2[j][e] = u;
    if (tid < 2) {
        float kb = 0.f;
        for (int d = 0; d < NDIM; d++) kb = fmaf(Wk[tid * NDIM + d], bq[d], kb);
        g_Kb[tid] = kb;
    }
}

// -------- graph node ranges via binary search (batch is sorted) --------
// Handles both int64 and silently-demoted int32 batch arrays.
__global__ void starts_kernel(const void* __restrict__ batch_raw, int ngraphs, int nnodes) {
    int g = blockIdx.x * blockDim.x + threadIdx.x;
    if (g > ngraphs) return;
    const int* b32 = (const int*)batch_raw;
    // Probe near the end (in-bounds for both layouts): int64 => odd words are high
    // halves == 0; int32 => values there are ~ngraphs (nonzero).
    int w = (nnodes & ~1) - 6;
    bool is64 = (b32[w + 1] == 0) && (b32[w + 3] == 0) && (b32[w + 5] == 0);
    const long long* b64 = (const long long*)batch_raw;
    long long gv = (long long)g;
    int lo = 0, hi = nnodes;
    while (lo < hi) {
        int mid = (lo + hi) >> 1;
        long long val = is64 ? b64[mid] : (long long)b32[mid];
        if (val < gv) lo = mid + 1; else hi = mid;
    }
    g_start[g] = lo;
}

// -------- build psi_j(beta) table: the whole charge_embed as f(j, beta) --------
__global__ void table_kernel(const float* __restrict__ Wv, const float* __restrict__ b1,
                             const float* __restrict__ W2, const float* __restrict__ b2) {
    int j = blockIdx.x / (TABK + 1);
    int t = blockIdx.x - j * (TABK + 1);
    int n = threadIdx.x;                       // 128 threads
    float tt = (float)t / (float)TABK;
    float beta = BMAXF * tt * tt;              // quadratic spacing: dense near 0
    __shared__ float h1s[NDIM];
    h1s[n] = silu_f(fmaf(beta, g_U2[j][n], b1[n]));
    __syncthreads();
    float y = 0.f;
    #pragma unroll 8
    for (int d = 0; d < NDIM; d++) y = fmaf(h1s[d], W2[d * NDIM + n], y);
    float h2 = silu_f(y + b2[n]);
    g_psi[j][t][n] = fmaf(beta, Wv[j * NDIM + n], h2);   // x + mlp(x)
}

// -------- fused main: per-block graphs, local segment-sum, table epilogue ----
#define GPB 2      // graphs per block
#define NW  8      // warps per block
#define NPW 4      // nodes per warp per iteration (MLP for latency hiding)

__global__ __launch_bounds__(256, 4) void main_kernel(
    const float* __restrict__ ns, const float* __restrict__ charge,
    float* __restrict__ out, int ngraphs) {
    int tid = threadIdx.x;
    int wid = tid >> 5, lane = tid & 31;
    __shared__ float warpsum[NW];
    // each lane keeps its 4-element slice of M0/M1 in registers
    float4 M0 = *reinterpret_cast<const float4*>(&g_M[0][lane * 4]);
    float4 M1 = *reinterpret_cast<const float4*>(&g_M[1][lane * 4]);
    float Kb0 = g_Kb[0], Kb1 = g_Kb[1];
    int gbase = blockIdx.x * GPB;

    for (int gg = 0; gg < GPB; gg++) {
        int g = gbase + gg;
        if (g >= ngraphs) break;
        float q  = charge[g];
        float r0 = fmaxf(q, 0.f), r1 = fmaxf(-q, 0.f);
        float c0 = fminf(r0, 1.f), c1 = fminf(r1, 1.f);   // relu / max(relu,1)
        float cg = c0 * Kb0 + c1 * Kb1;                   // bq . k_g
        int   jj = (q < 0.f) ? 1 : 0;
        float qb = fmaxf(r0, r1);                         // |q|
        int n0 = g_start[g], n1 = g_start[g + 1];

        // ---- phase A: block-local sum of softplus attention ----
        float acc = 0.f;
        for (int base = n0 + wid * NPW; base < n1; base += NW * NPW) {
            int cnt = n1 - base; if (cnt > NPW) cnt = NPW;
            float d0[NPW], d1[NPW];
            #pragma unroll
            for (int k = 0; k < NPW; k++) {
                d0[k] = 0.f; d1[k] = 0.f;
                if (k < cnt) {
                    float4 v = *reinterpret_cast<const float4*>(
                        &ns[(long)(base + k) * NDIM + lane * 4]);
                    d0[k] = v.x * M0.x + v.y * M0.y + v.z * M0.z + v.w * M0.w;
                    d1[k] = v.x * M1.x + v.y * M1.y + v.z * M1.z + v.w * M1.w;
                }
            }
            #pragma unroll
            for (int k = 0; k < NPW; k++) {
                #pragma unroll
                for (int o = 16; o > 0; o >>= 1) {
                    d0[k] += __shfl_xor_sync(0xffffffffu, d0[k], o);
                    d1[k] += __shfl_xor_sync(0xffffffffu, d1[k], o);
                }
            }
            #pragma unroll
            for (int k = 0; k < NPW; k++)
                if (k < cnt)
                    acc += softplus_f((c0 * d0[k] + c1 * d1[k] + cg) * ATT_SCALE);
        }
        if (lane == 0) warpsum[wid] = acc;
        __syncthreads();
        float asum = 0.f;
        #pragma unroll
        for (int w = 0; w < NW; w++) asum += warpsum[w];
        __syncthreads();
        float inv = 1.0f / asum;   // only used when nodes exist

        // ---- phase B: recompute attn (ns hot in L1/L2), table epilogue ----
        for (int base = n0 + wid * NPW; base < n1; base += NW * NPW) {
            int cnt = n1 - base; if (cnt > NPW) cnt = NPW;
            float d0[NPW], d1[NPW];
            float4 v[NPW];
            #pragma unroll
            for (int k = 0; k < NPW; k++) {
                d0[k] = 0.f; d1[k] = 0.f;
                if (k < cnt) {
                    v[k] = *reinterpret_cast<const float4*>(
                        &ns[(long)(base + k) * NDIM + lane * 4]);
                    d0[k] = v[k].x * M0.x + v[k].y * M0.y + v[k].z * M0.z + v[k].w * M0.w;
                    d1[k] = v[k].x * M1.x + v[k].y * M1.y + v[k].z * M1.z + v[k].w * M1.w;
                }
            }
            #pragma unroll
            for (int k = 0; k < NPW; k++) {
                #pragma unroll
                for (int o = 16; o > 0; o >>= 1) {
                    d0[k] += __shfl_xor_sync(0xffffffffu, d0[k], o);
                    d1[k] += __shfl_xor_sync(0xffffffffu, d1[k], o);
                }
            }
            #pragma unroll
            for (int k = 0; k < NPW; k++) {
                if (k < cnt) {
                    float attn = softplus_f((c0 * d0[k] + c1 * d1[k] + cg) * ATT_SCALE);
                    float beta = attn * inv * qb;         // beta <= |q| < BMAX
                    float tf = (float)TABK * sqrtf(beta * INV_BMAX);
                    int idx = (int)tf;
                    if (idx > TABK - 1) idx = TABK - 1;
                    float f = tf - (float)idx;
                    const float* pa = &g_psi[jj][idx][lane * 4];
                    float4 a = *reinterpret_cast<const float4*>(pa);
                    float4 b = *reinterpret_cast<const float4*>(pa + NDIM);
                    float4 o4;
                    o4.x = v[k].x + a.x + f * (b.x - a.x);
                    o4.y = v[k].y + a.y + f * (b.y - a.y);
                    o4.z = v[k].z + a.z + f * (b.z - a.z);
                    o4.w = v[k].w + a.w + f * (b.w - a.w);
                    *reinterpret_cast<float4*>(&out[(long)(base + k) * NDIM + lane * 4]) = o4;
                }
            }
        }
        __syncthreads();   // protect warpsum before next graph
    }
}

extern "C" void kernel_launch(void* const* d_in, const int* in_sizes, int n_in,
                              void* d_out, int out_size) {
    const float* ns     = (const float*)d_in[0];
    const float* charge = (const float*)d_in[1];
    const void*  batch  = (const void*) d_in[2];
    const float* Wq     = (const float*)d_in[3];
    const float* bq     = (const float*)d_in[4];
    const float* Wk     = (const float*)d_in[5];
    const float* Wv     = (const float*)d_in[6];
    const float* W1     = (const float*)d_in[7];
    const float* b1     = (const float*)d_in[8];
    const float* W2     = (const float*)d_in[9];
    const float* b2     = (const float*)d_in[10];
    float* out = (float*)d_out;

    int nnodes  = in_sizes[0] / NDIM;
    int ngraphs = in_sizes[1];

    prep_kernel<<<1, 256>>>(Wq, bq, Wk, Wv, W1);
    starts_kernel<<<(ngraphs + 1 + 255) / 256, 256>>>(batch, ngraphs, nnodes);
    table_kernel<<<2 * (TABK + 1), 128>>>(Wv, b1, W2, b2);
    main_kernel<<<(ngraphs + GPB - 1) / GPB, 256>>>(ns, charge, out, ngraphs);
}

// round 2
// speedup vs baseline: 1.1938x; 1.1938x over previous
#include <cuda_runtime.h>
#include <math.h>
#include <stdint.h>

#define NDIM     128
#define TABK     1024
#define BMAXF    8.0f
#define INV_BMAX 0.125f
#define ATT_SCALE 0.08838834764831845f  // 1/sqrt(128)
#define MAX_GRAPHS 10000
#define CAP      1024                    // smem attn cache per graph (nodes)

// -------- persistent device scratch (static allocation only) --------
__device__ float g_M[2][NDIM];               // Wq @ Wk^T   (rank-2 query projection)
__device__ float g_U2[2][NDIM];              // Wv @ W1
__device__ float g_Kb[2];                    // Wk @ bq
__device__ int   g_start[MAX_GRAPHS + 1];    // per-graph node offsets
__device__ float g_psi[2][TABK + 1][NDIM];   // charge_embed table psi_j(beta)

__device__ __forceinline__ float silu_f(float z) {
    return z / (1.0f + expf(-z));
}
__device__ __forceinline__ float softplus_fast(float s) {
    // softplus = max(s,0) + log1p(exp(-|s|)); fast intrinsics, ~1e-6 abs err
    return fmaxf(s, 0.0f) + __logf(1.0f + __expf(-fabsf(s)));
}

// -------- tiny precompute: M, U2, Kb --------
__global__ void prep_kernel(const float* __restrict__ Wq, const float* __restrict__ bq,
                            const float* __restrict__ Wk, const float* __restrict__ Wv,
                            const float* __restrict__ W1) {
    int tid = threadIdx.x;       // 256 threads
    int j = tid >> 7, e = tid & 127;
    float m = 0.f;
    #pragma unroll 8
    for (int d = 0; d < NDIM; d++) m = fmaf(Wq[e * NDIM + d], Wk[j * NDIM + d], m);
    g_M[j][e] = m;
    float u = 0.f;
    #pragma unroll 8
    for (int ee = 0; ee < NDIM; ee++) u = fmaf(Wv[j * NDIM + ee], W1[ee * NDIM + e], u);
    g_U2[j][e] = u;
    if (tid < 2) {
        float kb = 0.f;
        for (int d = 0; d < NDIM; d++) kb = fmaf(Wk[tid * NDIM + d], bq[d], kb);
        g_Kb[tid] = kb;
    }
}

// -------- graph node ranges via binary search (batch is sorted) --------
__global__ void starts_kernel(const void* __restrict__ batch_raw, int ngraphs, int nnodes) {
    int g = blockIdx.x * blockDim.x + threadIdx.x;
    if (g > ngraphs) return;
    const int* b32 = (const int*)batch_raw;
    int w = (nnodes >= 8) ? ((nnodes & ~1) - 6) : 0;
    bool is64 = (b32[w + 1] == 0) && (b32[w + 3] == 0) && (b32[w + 5] == 0);
    const long long* b64 = (const long long*)batch_raw;
    long long gv = (long long)g;
    int lo = 0, hi = nnodes;
    while (lo < hi) {
        int mid = (lo + hi) >> 1;
        long long val = is64 ? b64[mid] : (long long)b32[mid];
        if (val < gv) lo = mid + 1; else hi = mid;
    }
    g_start[g] = lo;
}

// -------- build psi_j(beta): 16 beta-points per block, W2 L1-resident --------
#define TPB_T 16
__global__ void table_kernel(const float* __restrict__ Wv, const float* __restrict__ b1,
                             const float* __restrict__ W2, const float* __restrict__ b2) {
    const int nTB = (TABK + 1 + TPB_T - 1) / TPB_T;
    int j  = blockIdx.x / nTB;
    int tb = blockIdx.x - j * nTB;
    int n  = threadIdx.x;                      // 128 threads
    __shared__ float h1s[TPB_T][NDIM];
    float u2 = g_U2[j][n];
    float b1n = b1[n];
    #pragma unroll
    for (int tt = 0; tt < TPB_T; tt++) {
        int t = tb * TPB_T + tt;
        if (t > TABK) break;
        float x = (float)t / (float)TABK;
        float beta = BMAXF * x * x;
        h1s[tt][n] = silu_f(fmaf(beta, u2, b1n));
    }
    __syncthreads();
    float b2n = b2[n];
    float wv = Wv[j * NDIM + n];
    for (int tt = 0; tt < TPB_T; tt++) {
        int t = tb * TPB_T + tt;
        if (t > TABK) break;
        float y = 0.f;
        #pragma unroll 8
        for (int d = 0; d < NDIM; d++) y = fmaf(h1s[tt][d], W2[d * NDIM + n], y);
        float x = (float)t / (float)TABK;
        float beta = BMAXF * x * x;
        g_psi[j][t][n] = fmaf(beta, wv, silu_f(y + b2n));
    }
}

// -------- fused main: 1 graph per 128-thread block, 8-lane-group dots --------
#define NW  4       // warps per block
#define NPB (NW*4)  // nodes per block iteration (each warp: 4 nodes via 8-lane groups)

__global__ __launch_bounds__(128, 8) void main_kernel(
    const float* __restrict__ ns, const float* __restrict__ charge,
    float* __restrict__ out, int ngraphs) {
    int tid  = threadIdx.x;
    int wid  = tid >> 5, lane = tid & 31;
    int l8   = lane & 7;            // lane within 8-lane group
    int grp  = lane >> 3;           // group 0..3 within warp
    __shared__ float warpsum[NW];
    __shared__ float sm_attn[CAP];

    int g = blockIdx.x;
    if (g >= ngraphs) return;

    float q  = charge[g];
    float r0 = fmaxf(q, 0.f), r1 = fmaxf(-q, 0.f);
    float c0 = fminf(r0, 1.f), c1 = fminf(r1, 1.f);
    float cg = c0 * g_Kb[0] + c1 * g_Kb[1];
    int   jj = (q < 0.f) ? 1 : 0;
    float qb = fmaxf(r0, r1);
    int n0 = g_start[g], n1 = g_start[g + 1];

    // combined projection Mc = c0*M0 + c1*M1, this lane's 16-float slice
    float4 Mc[4];
    #pragma unroll
    for (int jc = 0; jc < 4; jc++) {
        int e = jc * 32 + l8 * 4;
        float4 a = *reinterpret_cast<const float4*>(&g_M[0][e]);
        float4 b = *reinterpret_cast<const float4*>(&g_M[1][e]);
        Mc[jc].x = c0 * a.x + c1 * b.x;
        Mc[jc].y = c0 * a.y + c1 * b.y;
        Mc[jc].z = c0 * a.z + c1 * b.z;
        Mc[jc].w = c0 * a.w + c1 * b.w;
    }

    // ---- phase A: block-local softplus-attention sum ----
    float acc = 0.f;
    for (int base = n0; base < n1; base += NPB) {
        int node = base + wid * 4 + grp;
        bool valid = node < n1;
        float s = 0.f;
        if (valid) {
            const float* row = ns + (long)node * NDIM + l8 * 4;
            #pragma unroll
            for (int jc = 0; jc < 4; jc++) {
                float4 v = *reinterpret_cast<const float4*>(row + jc * 32);
                s += v.x * Mc[jc].x + v.y * Mc[jc].y + v.z * Mc[jc].z + v.w * Mc[jc].w;
            }
        }
        s += __shfl_xor_sync(0xffffffffu, s, 1);
        s += __shfl_xor_sync(0xffffffffu, s, 2);
        s += __shfl_xor_sync(0xffffffffu, s, 4);
        if (valid && l8 == 0) {
            float attn = softplus_fast((s + cg) * ATT_SCALE);
            acc += attn;
            int li = node - n0;
            if (li < CAP) sm_attn[li] = attn;
        }
    }
    // warp reduce (non-contributor lanes hold 0)
    #pragma unroll
    for (int o = 16; o > 0; o >>= 1) acc += __shfl_xor_sync(0xffffffffu, acc, o);
    if (lane == 0) warpsum[wid] = acc;
    __syncthreads();
    float asum = warpsum[0] + warpsum[1] + warpsum[2] + warpsum[3];
    float inv = 1.0f / asum;

    // ---- phase B: table epilogue (ns hot in L2) ----
    for (int base = n0; base < n1; base += NPB) {
        int node = base + wid * 4 + grp;
        if (node >= n1) continue;
        int li = node - n0;
        float attn;
        if (li < CAP) {
            attn = sm_attn[li];     // broadcast within group
        } else {
            // rare fallback: recompute dot
            float s = 0.f;
            const float* row = ns + (long)node * NDIM + l8 * 4;
            #pragma unroll
            for (int jc = 0; jc < 4; jc++) {
                float4 v = *reinterpret_cast<const float4*>(row + jc * 32);
                s += v.x * Mc[jc].x + v.y * Mc[jc].y + v.z * Mc[jc].z + v.w * Mc[jc].w;
            }
            s += __shfl_xor_sync(0xffffffffu, s, 1);
            s += __shfl_xor_sync(0xffffffffu, s, 2);
            s += __shfl_xor_sync(0xffffffffu, s, 4);
            attn = softplus_fast((s + cg) * ATT_SCALE);
        }
        float beta = attn * inv * qb;                 // <= |q| < BMAX
        float tf = (float)TABK * sqrtf(beta * INV_BMAX);
        int idx = (int)tf;
        if (idx > TABK - 1) idx = TABK - 1;
        float f = tf - (float)idx;
        const float* pa = &g_psi[jj][idx][0];
        const float* row = ns + (long)node * NDIM;
        float* orow = out + (long)node * NDIM;
        #pragma unroll
        for (int jc = 0; jc < 4; jc++) {
            int e = jc * 32 + l8 * 4;
            float4 v = *reinterpret_cast<const float4*>(row + e);
            float4 a = *reinterpret_cast<const float4*>(pa + e);
            float4 b = *reinterpret_cast<const float4*>(pa + NDIM + e);
            float4 o4;
            o4.x = v.x + fmaf(f, b.x - a.x, a.x);
            o4.y = v.y + fmaf(f, b.y - a.y, a.y);
            o4.z = v.z + fmaf(f, b.z - a.z, a.z);
            o4.w = v.w + fmaf(f, b.w - a.w, a.w);
            *reinterpret_cast<float4*>(orow + e) = o4;
        }
    }
}

extern "C" void kernel_launch(void* const* d_in, const int* in_sizes, int n_in,
                              void* d_out, int out_size) {
    const float* ns     = (const float*)d_in[0];
    const float* charge = (const float*)d_in[1];
    const void*  batch  = (const void*) d_in[2];
    const float* Wq     = (const float*)d_in[3];
    const float* bq     = (const float*)d_in[4];
    const float* Wk     = (const float*)d_in[5];
    const float* Wv     = (const float*)d_in[6];
    const float* W1     = (const float*)d_in[7];
    const float* b1     = (const float*)d_in[8];
    const float* W2     = (const float*)d_in[9];
    const float* b2     = (const float*)d_in[10];
    float* out = (float*)d_out;

    int nnodes  = in_sizes[0] / NDIM;
    int ngraphs = in_sizes[1];

    prep_kernel<<<1, 256>>>(Wq, bq, Wk, Wv, W1);
    starts_kernel<<<(ngraphs + 1 + 255) / 256, 256>>>(batch, ngraphs, nnodes);
    const int nTB = (TABK + 1 + TPB_T - 1) / TPB_T;
    table_kernel<<<2 * nTB, 128>>>(Wv, b1, W2, b2);
    main_kernel<<<ngraphs, 128>>>(ns, charge, out, ngraphs);
}

// round 3
// speedup vs baseline: 1.3944x; 1.1681x over previous
#include <cuda_runtime.h>
#include <math.h>
#include <stdint.h>

#define NDIM     128
#define TABK     1024
#define BMAXF    8.0f
#define INV_BMAX 0.125f
#define ATT_SCALE 0.08838834764831845f  // 1/sqrt(128)
#define MAX_GRAPHS 10000
#define CAP      1024                    // smem attn cache per graph (nodes)

// -------- persistent device scratch (static allocation only) --------
__device__ float g_M[2][NDIM];               // Wq @ Wk^T
__device__ float g_Kb[2];                    // Wk @ bq
__device__ int   g_start[MAX_GRAPHS + 1];    // per-graph node offsets
__device__ float g_psi[2][TABK + 1][NDIM];   // charge_embed table psi_j(beta)

__device__ __forceinline__ float silu_f(float z) {
    return z / (1.0f + expf(-z));
}
__device__ __forceinline__ float softplus_fast(float s) {
    return fmaxf(s, 0.0f) + __logf(1.0f + __expf(-fabsf(s)));
}

// ================= fused aux kernel: table | starts | prep =================
// block roles by blockIdx.x:
//   [0, 2*nTB)            table builder (recomputes its own U2 inline)
//   [2*nTB, 2*nTB+SB)     starts (binary search)
//   2*nTB+SB              prep (M, Kb)
#define TPB_T 16
#define NTB   ((TABK + 1 + TPB_T - 1) / TPB_T)
#define SB    40

__global__ __launch_bounds__(256) void aux_kernel(
    const void* __restrict__ batch_raw, int ngraphs, int nnodes,
    const float* __restrict__ Wq, const float* __restrict__ bq,
    const float* __restrict__ Wk, const float* __restrict__ Wv,
    const float* __restrict__ W1, const float* __restrict__ b1,
    const float* __restrict__ W2, const float* __restrict__ b2) {
    int bid = blockIdx.x;
    int tid = threadIdx.x;

    if (bid < 2 * NTB) {
        // ---------------- table role ----------------
        if (tid >= 128) return;
        int j  = bid / NTB;
        int tb = bid - j * NTB;
        int n  = tid;
        // U2[j][n] = sum_ee Wv[j][ee] * W1[ee][n]   (coalesced W1 column reads)
        float u2 = 0.f;
        #pragma unroll 8
        for (int ee = 0; ee < NDIM; ee++) u2 = fmaf(Wv[j * NDIM + ee], W1[ee * NDIM + n], u2);
        __shared__ float h1s[TPB_T][NDIM];
        float b1n = b1[n];
        #pragma unroll
        for (int tt = 0; tt < TPB_T; tt++) {
            int t = tb * TPB_T + tt;
            if (t > TABK) break;
            float x = (float)t / (float)TABK;
            float beta = BMAXF * x * x;
            h1s[tt][n] = silu_f(fmaf(beta, u2, b1n));
        }
        __syncthreads();
        float b2n = b2[n];
        float wv = Wv[j * NDIM + n];
        for (int tt = 0; tt < TPB_T; tt++) {
            int t = tb * TPB_T + tt;
            if (t > TABK) break;
            float y = 0.f;
            #pragma unroll 8
            for (int d = 0; d < NDIM; d++) y = fmaf(h1s[tt][d], W2[d * NDIM + n], y);
            float x = (float)t / (float)TABK;
            float beta = BMAXF * x * x;
            g_psi[j][t][n] = fmaf(beta, wv, silu_f(y + b2n));
        }
    } else if (bid < 2 * NTB + SB) {
        // ---------------- starts role ----------------
        int g = (bid - 2 * NTB) * 256 + tid;
        if (g > ngraphs) return;
        const int* b32 = (const int*)batch_raw;
        int w = (nnodes >= 8) ? ((nnodes & ~1) - 6) : 0;
        bool is64 = (b32[w + 1] == 0) && (b32[w + 3] == 0) && (b32[w + 5] == 0);
        const long long* b64 = (const long long*)batch_raw;
        long long gv = (long long)g;
        int lo = 0, hi = nnodes;
        while (lo < hi) {
            int mid = (lo + hi) >> 1;
            long long val = is64 ? b64[mid] : (long long)b32[mid];
            if (val < gv) lo = mid + 1; else hi = mid;
        }
        g_start[g] = lo;
    } else {
        // ---------------- prep role (M, Kb) ----------------
        int j = tid >> 7, e = tid & 127;
        float m = 0.f;
        #pragma unroll 8
        for (int d = 0; d < NDIM; d++) m = fmaf(Wq[e * NDIM + d], Wk[j * NDIM + d], m);
        g_M[j][e] = m;
        if (tid < 2) {
            float kb = 0.f;
            for (int d = 0; d < NDIM; d++) kb = fmaf(Wk[tid * NDIM + d], bq[d], kb);
            g_Kb[tid] = kb;
        }
    }
}

// ========== fused main: 1 graph per 128-thread block, 8-lane-group dots =====
#define NW  4       // warps per block
#define NPB (NW*4)  // nodes per block iteration

__global__ __launch_bounds__(128, 8) void main_kernel(
    const float* __restrict__ ns, const float* __restrict__ charge,
    float* __restrict__ out, int ngraphs) {
    int tid  = threadIdx.x;
    int wid  = tid >> 5, lane = tid & 31;
    int l8   = lane & 7;
    int grp  = lane >> 3;
    __shared__ float warpsum[NW];
    __shared__ float sm_attn[CAP];

    int g = blockIdx.x;
    if (g >= ngraphs) return;

    float q  = charge[g];
    float r0 = fmaxf(q, 0.f), r1 = fmaxf(-q, 0.f);
    float c0 = fminf(r0, 1.f), c1 = fminf(r1, 1.f);
    float cg = c0 * g_Kb[0] + c1 * g_Kb[1];
    int   jj = (q < 0.f) ? 1 : 0;
    float qb = fmaxf(r0, r1);
    int n0 = g_start[g], n1 = g_start[g + 1];

    // combined projection Mc = c0*M0 + c1*M1, this lane's 16-float slice
    float4 Mc[4];
    #pragma unroll
    for (int jc = 0; jc < 4; jc++) {
        int e = jc * 32 + l8 * 4;
        float4 a = *reinterpret_cast<const float4*>(&g_M[0][e]);
        float4 b = *reinterpret_cast<const float4*>(&g_M[1][e]);
        Mc[jc].x = c0 * a.x + c1 * b.x;
        Mc[jc].y = c0 * a.y + c1 * b.y;
        Mc[jc].z = c0 * a.z + c1 * b.z;
        Mc[jc].w = c0 * a.w + c1 * b.w;
    }

    // ---- phase A: block-local softplus-attention sum (loads cache in L2) ----
    float acc = 0.f;
    for (int base = n0; base < n1; base += NPB) {
        int node = base + wid * 4 + grp;
        bool valid = node < n1;
        float s = 0.f;
        if (valid) {
            const float* row = ns + (long)node * NDIM + l8 * 4;
            #pragma unroll
            for (int jc = 0; jc < 4; jc++) {
                float4 v = *reinterpret_cast<const float4*>(row + jc * 32);
                s += v.x * Mc[jc].x + v.y * Mc[jc].y + v.z * Mc[jc].z + v.w * Mc[jc].w;
            }
        }
        s += __shfl_xor_sync(0xffffffffu, s, 1);
        s += __shfl_xor_sync(0xffffffffu, s, 2);
        s += __shfl_xor_sync(0xffffffffu, s, 4);
        if (valid && l8 == 0) {
            float attn = softplus_fast((s + cg) * ATT_SCALE);
            acc += attn;
            int li = node - n0;
            if (li < CAP) sm_attn[li] = attn;
        }
    }
    #pragma unroll
    for (int o = 16; o > 0; o >>= 1) acc += __shfl_xor_sync(0xffffffffu, acc, o);
    if (lane == 0) warpsum[wid] = acc;
    __syncthreads();
    float asum = warpsum[0] + warpsum[1] + warpsum[2] + warpsum[3];
    float inv = 1.0f / asum;

    // ---- phase B: table epilogue; last-use reads evict-first, streaming out --
    for (int base = n0; base < n1; base += NPB) {
        int node = base + wid * 4 + grp;
        if (node >= n1) continue;
        int li = node - n0;
        float attn;
        if (li < CAP) {
            attn = sm_attn[li];
        } else {
            float s = 0.f;
            const float* row = ns + (long)node * NDIM + l8 * 4;
            #pragma unroll
            for (int jc = 0; jc < 4; jc++) {
                float4 v = __ldcs(reinterpret_cast<const float4*>(row + jc * 32));
                s += v.x * Mc[jc].x + v.y * Mc[jc].y + v.z * Mc[jc].z + v.w * Mc[jc].w;
            }
            s += __shfl_xor_sync(0xffffffffu, s, 1);
            s += __shfl_xor_sync(0xffffffffu, s, 2);
            s += __shfl_xor_sync(0xffffffffu, s, 4);
            attn = softplus_fast((s + cg) * ATT_SCALE);
        }
        float beta = attn * inv * qb;
        float tf = (float)TABK * sqrtf(beta * INV_BMAX);
        int idx = (int)tf;
        if (idx > TABK - 1) idx = TABK - 1;
        float f = tf - (float)idx;
        const float* pa = &g_psi[jj][idx][0];
        const float* row = ns + (long)node * NDIM;
        float* orow = out + (long)node * NDIM;
        #pragma unroll
        for (int jc = 0; jc < 4; jc++) {
            int e = jc * 32 + l8 * 4;
            float4 v = __ldcs(reinterpret_cast<const float4*>(row + e));
            float4 a = *reinterpret_cast<const float4*>(pa + e);
            float4 b = *reinterpret_cast<const float4*>(pa + NDIM + e);
            float4 o4;
            o4.x = v.x + fmaf(f, b.x - a.x, a.x);
            o4.y = v.y + fmaf(f, b.y - a.y, a.y);
            o4.z = v.z + fmaf(f, b.z - a.z, a.z);
            o4.w = v.w + fmaf(f, b.w - a.w, a.w);
            __stcs(reinterpret_cast<float4*>(orow + e), o4);
        }
    }
}

extern "C" void kernel_launch(void* const* d_in, const int* in_sizes, int n_in,
                              void* d_out, int out_size) {
    const float* ns     = (const float*)d_in[0];
    const float* charge = (const float*)d_in[1];
    const void*  batch  = (const void*) d_in[2];
    const float* Wq     = (const float*)d_in[3];
    const float* bq     = (const float*)d_in[4];
    const float* Wk     = (const float*)d_in[5];
    const float* Wv     = (const float*)d_in[6];
    const float* W1     = (const float*)d_in[7];
    const float* b1     = (const float*)d_in[8];
    const float* W2     = (const float*)d_in[9];
    const float* b2     = (const float*)d_in[10];
    float* out = (float*)d_out;

    int nnodes  = in_sizes[0] / NDIM;
    int ngraphs = in_sizes[1];

    aux_kernel<<<2 * NTB + SB + 1, 256>>>(batch, ngraphs, nnodes,
                                          Wq, bq, Wk, Wv, W1, b1, W2, b2);
    main_kernel<<<ngraphs, 128>>>(ns, charge, out, ngraphs);
}